// round 11
// baseline (speedup 1.0000x reference)
#include <cuda_runtime.h>
#include <cuda_bf16.h>
#include <cstdint>

// ===================== problem constants =====================
static constexpr int GM = 4096, GN = 4096, GK = 4096;

// CTA 128x128, warp tile 64x64 (4 warps, 2x2), K-stage 32, fused BFP quant.
// 2 CTAs/SM (128 thr * 256 regs * 2 = 64K regs; 32KB smem * 2 = 64KB).
static constexpr int BM = 128;
static constexpr int BN = 128;
static constexpr int BK = 32;
static constexpr int KTILES = GK / BK;          // 128

static constexpr int ROWB   = BK * 2;           // 64 bytes per bf16 row
static constexpr int A_TILE = BM * ROWB;        // 8192
static constexpr int STAGE  = 2 * A_TILE;       // A + B = 16384
static constexpr int SMEM_TOTAL = 2 * STAGE;    // double buffer = 32768

// ===================== PTX helpers =====================
__device__ __forceinline__ uint32_t smem_u32(const void* p) {
    uint32_t a;
    asm("{ .reg .u64 t; cvta.to.shared.u64 t, %1; cvt.u32.u64 %0, t; }" : "=r"(a) : "l"(p));
    return a;
}

#define LDM_X4(r0, r1, r2, r3, addr) \
    asm volatile("ldmatrix.sync.aligned.m8n8.x4.shared.b16 {%0,%1,%2,%3}, [%4];" \
                 : "=r"(r0), "=r"(r1), "=r"(r2), "=r"(r3) : "r"(addr))

#define MMA16816(d0, d1, d2, d3, a0, a1, a2, a3, b0, b1) \
    asm volatile( \
        "mma.sync.aligned.m16n8k16.row.col.f32.bf16.bf16.f32 " \
        "{%0,%1,%2,%3}, {%4,%5,%6,%7}, {%8,%9}, {%0,%1,%2,%3};" \
        : "+f"(d0), "+f"(d1), "+f"(d2), "+f"(d3) \
        : "r"(a0), "r"(a1), "r"(a2), "r"(a3), "r"(b0), "r"(b1))

#define STS64(addr, r0, r1) \
    asm volatile("st.shared.v2.b32 [%0], {%1,%2};" \
                 :: "r"(addr), "r"(r0), "r"(r1) : "memory")

// Quantize one float4 (thread's quarter of a 16-float BFP group; quad of
// lanes shares the group) and store 4 bf16 (8B) to swizzled smem.
// Exact round-half-even: x*inv is exact (power-of-2), magic-add rounds,
// single upper clamp at +127 (lower -128 unreachable & allowed).
#define QUNIT(v, saddr) do {                                                   \
        float _m = fmaxf(fmaxf(fabsf((v).x), fabsf((v).y)),                    \
                         fmaxf(fabsf((v).z), fabsf((v).w)));                   \
        _m = fmaxf(_m, __shfl_xor_sync(0xffffffffu, _m, 1));                   \
        _m = fmaxf(_m, __shfl_xor_sync(0xffffffffu, _m, 2));                   \
        uint32_t _eb = __float_as_uint(_m) & 0x7f800000u;                      \
        float _inv = __uint_as_float(0x82000000u - _eb);   /* 2^(6-e) */       \
        float _scl = __uint_as_float(_eb - 0x03000000u);   /* 2^(e-6) */       \
        float _q0 = (fminf(fmaf((v).x, _inv, 12582912.f), 12583039.f) - 12582912.f) * _scl; \
        float _q1 = (fminf(fmaf((v).y, _inv, 12582912.f), 12583039.f) - 12582912.f) * _scl; \
        float _q2 = (fminf(fmaf((v).z, _inv, 12582912.f), 12583039.f) - 12582912.f) * _scl; \
        float _q3 = (fminf(fmaf((v).w, _inv, 12582912.f), 12583039.f) - 12582912.f) * _scl; \
        uint32_t _p0, _p1;                                                     \
        asm("cvt.rn.satfinite.bf16x2.f32 %0, %1, %2;" : "=r"(_p0) : "f"(_q1), "f"(_q0)); \
        asm("cvt.rn.satfinite.bf16x2.f32 %0, %1, %2;" : "=r"(_p1) : "f"(_q3), "f"(_q2)); \
        STS64((saddr), _p0, _p1);                                              \
    } while (0)

// ===================== fused BFP GEMM ======================================
// 128 threads = 4 warps (2M x 2N), warp tile 64x64, acc 128 f32/thread.
// Smem rows are 64B (32 bf16); swizzle: addr ^= ((row>>1)&3)<<4 — bijective
// bank-chunk spread for both ldmatrix (8 rows x 16B) and quant STS.
__global__ void __launch_bounds__(128, 2)
bfp_gemm_fused(const float* __restrict__ x, const float* __restrict__ w,
               const float* __restrict__ bias, float* __restrict__ out) {
    extern __shared__ char smem[];
    uint32_t sb = smem_u32(smem);
    int tid = threadIdx.x;
    int wid = tid >> 5;
    int lid = tid & 31;
    int wm = wid >> 1;       // M warp: 0..1 (64 rows each)
    int wn = wid & 1;        // N warp: 0..1 (64 cols each)
    int tile_n = blockIdx.x;
    int tile_m = blockIdx.y;

    // ---- quant mapping: 8 threads per row, one float4 each; units step 16 rows
    int qr = tid >> 3;               // base row 0..15
    int qs = tid & 7;                // f4 slot within the 8-f4 (128B) k-slab
    const float4* aP = (const float4*)x + (size_t)(tile_m * BM + qr) * (GK / 4) + qs;
    const float4* bP = (const float4*)w + (size_t)(tile_n * BN + qr) * (GK / 4) + qs;
    const size_t ustep = (size_t)16 * (GK / 4);        // +16 rows, f4 units
    // swizzle mask ((row>>1)&3)<<4 is invariant across +16-row units
    uint32_t qmask = (uint32_t)((qr >> 1) & 3) << 4;
    uint32_t sts0 = (uint32_t)qr * ROWB + ((((uint32_t)qs >> 1) << 4) ^ qmask)
                  + ((uint32_t)qs & 1) * 8;            // + i*1024 per unit

    // ---- ldmatrix address components ----
    uint32_t khx = (uint32_t)((lid >> 4) << 4);        // A k-half (16B)
    uint32_t a_off[4], a_mk[4];
#pragma unroll
    for (int am = 0; am < 4; am++) {
        int r = wm * 64 + am * 16 + (lid & 15);
        a_off[am] = (uint32_t)r * ROWB;
        a_mk[am]  = (uint32_t)((r >> 1) & 3) << 4;
    }
    uint32_t bkx = (uint32_t)(((lid >> 3) & 1) << 4);  // B k-half
    uint32_t b_off[4], b_mk[4];
#pragma unroll
    for (int bn = 0; bn < 4; bn++) {
        int r = wn * 64 + bn * 16 + ((lid >> 4) & 1) * 8 + (lid & 7);
        b_off[bn] = (uint32_t)r * ROWB;
        b_mk[bn]  = (uint32_t)((r >> 1) & 3) << 4;
    }

    float acc[4][8][4];
#pragma unroll
    for (int am = 0; am < 4; am++)
#pragma unroll
        for (int j = 0; j < 8; j++)
#pragma unroll
            for (int c = 0; c < 4; c++) acc[am][j][c] = 0.f;

    float4 fa[8], fb[8];     // staged fp32: 8 units A + 8 units B

#define LOAD_TILE(kt) do {                                                     \
        _Pragma("unroll")                                                      \
        for (int i = 0; i < 8; i++) fa[i] = aP[(size_t)(kt) * 8 + i * ustep];  \
        _Pragma("unroll")                                                      \
        for (int i = 0; i < 8; i++) fb[i] = bP[(size_t)(kt) * 8 + i * ustep];  \
    } while (0)

    // ---- prologue: tile 0 into buffer 0 ----
    LOAD_TILE(0);
#pragma unroll
    for (int i = 0; i < 8; i++) QUNIT(fa[i], sb + sts0 + (uint32_t)(i * 1024));
#pragma unroll
    for (int i = 0; i < 8; i++) QUNIT(fb[i], sb + A_TILE + sts0 + (uint32_t)(i * 1024));
    __syncthreads();

    // ---- main loop ----
    for (int kt = 0; kt < KTILES; kt++) {
        if (kt + 1 < KTILES) LOAD_TILE(kt + 1);

        uint32_t nxt = sb + (uint32_t)((kt + 1) & 1) * STAGE;
        // quantize A early (its buffer is free since the previous barrier);
        // B is quantized after the MMA phase to shorten register lifetimes.
        if (kt + 1 < KTILES) {
#pragma unroll
            for (int i = 0; i < 8; i++) QUNIT(fa[i], nxt + sts0 + (uint32_t)(i * 1024));
        }

        uint32_t Ab = sb + (uint32_t)(kt & 1) * STAGE;
        uint32_t Bb = Ab + A_TILE;
#pragma unroll
        for (int ks = 0; ks < 2; ks++) {
            uint32_t ks32 = (uint32_t)ks * 32u;
            uint32_t A[4][4], B[4][4];
#pragma unroll
            for (int am = 0; am < 4; am++)
                LDM_X4(A[am][0], A[am][1], A[am][2], A[am][3],
                       Ab + a_off[am] + ((ks32 + khx) ^ a_mk[am]));
#pragma unroll
            for (int bn = 0; bn < 4; bn++)
                LDM_X4(B[bn][0], B[bn][1], B[bn][2], B[bn][3],
                       Bb + b_off[bn] + ((ks32 + bkx) ^ b_mk[bn]));
#pragma unroll
            for (int am = 0; am < 4; am++)
#pragma unroll
                for (int j = 0; j < 8; j++)
                    MMA16816(acc[am][j][0], acc[am][j][1], acc[am][j][2], acc[am][j][3],
                             A[am][0], A[am][1], A[am][2], A[am][3],
                             B[j >> 1][(j & 1) * 2], B[j >> 1][(j & 1) * 2 + 1]);
        }

        if (kt + 1 < KTILES) {
#pragma unroll
            for (int i = 0; i < 8; i++)
                QUNIT(fb[i], nxt + A_TILE + sts0 + (uint32_t)(i * 1024));
        }
        __syncthreads();
    }
#undef LOAD_TILE

    // ---- epilogue ----
#pragma unroll
    for (int am = 0; am < 4; am++) {
        int row0 = tile_m * BM + wm * 64 + am * 16 + (lid >> 2);
#pragma unroll
        for (int j = 0; j < 8; j++) {
            int col = tile_n * BN + wn * 64 + j * 8 + (lid & 3) * 2;
            float2 b2 = *(const float2*)(bias + col);
            float2 v0 = make_float2(acc[am][j][0] + b2.x, acc[am][j][1] + b2.y);
            float2 v1 = make_float2(acc[am][j][2] + b2.x, acc[am][j][3] + b2.y);
            *(float2*)(out + (size_t)row0 * GN + col)       = v0;
            *(float2*)(out + (size_t)(row0 + 8) * GN + col) = v1;
        }
    }
}

// ===================== launch =====================
extern "C" void kernel_launch(void* const* d_in, const int* in_sizes, int n_in,
                              void* d_out, int out_size) {
    const float* x    = (const float*)d_in[0];   // [4096, 4096]
    const float* w    = (const float*)d_in[1];   // [4096, 4096]
    const float* bias = (const float*)d_in[2];   // [4096]
    float* out = (float*)d_out;                  // [4096, 4096]

    (void)in_sizes; (void)n_in; (void)out_size;

    dim3 grid(GN / BN, GM / BM);  // (32, 32), x fastest => B-tile L2 reuse
    bfp_gemm_fused<<<grid, 128, SMEM_TOTAL>>>(x, w, bias, out);
}

// round 12
// speedup vs baseline: 1.0938x; 1.0938x over previous
#include <cuda_runtime.h>
#include <cuda_bf16.h>
#include <cstdint>

// ===================== problem constants =====================
static constexpr int GM = 4096, GN = 4096, GK = 4096;

// CTA 128x256, 8 warps as 2(M) x 4(N), warp tile 64x64, K-stage 64.
// Fused BFP quant; double-buffered bf16 smem (96KB).
static constexpr int BM = 128;
static constexpr int BN = 256;
static constexpr int BK = 64;
static constexpr int KTILES = GK / BK;            // 64

static constexpr int A_TILE = BM * BK * 2;        // 16384
static constexpr int B_TILE = BN * BK * 2;        // 32768
static constexpr int STAGE  = A_TILE + B_TILE;    // 49152
static constexpr int SMEM_TOTAL = 2 * STAGE;      // 98304

// ===================== PTX helpers =====================
__device__ __forceinline__ uint32_t smem_u32(const void* p) {
    uint32_t a;
    asm("{ .reg .u64 t; cvta.to.shared.u64 t, %1; cvt.u32.u64 %0, t; }" : "=r"(a) : "l"(p));
    return a;
}

#define LDM_X4(r0, r1, r2, r3, addr) \
    asm volatile("ldmatrix.sync.aligned.m8n8.x4.shared.b16 {%0,%1,%2,%3}, [%4];" \
                 : "=r"(r0), "=r"(r1), "=r"(r2), "=r"(r3) : "r"(addr))

#define MMA16816(d0, d1, d2, d3, a0, a1, a2, a3, b0, b1) \
    asm volatile( \
        "mma.sync.aligned.m16n8k16.row.col.f32.bf16.bf16.f32 " \
        "{%0,%1,%2,%3}, {%4,%5,%6,%7}, {%8,%9}, {%0,%1,%2,%3};" \
        : "+f"(d0), "+f"(d1), "+f"(d2), "+f"(d3) \
        : "r"(a0), "r"(a1), "r"(a2), "r"(a3), "r"(b0), "r"(b1))

// Quantize one float4 (quarter of a 16-float BFP group shared by a lane quad)
// and store 8B to swizzled smem. Exact round-half-even via magic-add; x*inv
// exact (power-of-2 scale); single upper clamp (+127); -128 unreachable.
#define QUNIT(v, saddr) do {                                                   \
        float _m = fmaxf(fmaxf(fabsf((v).x), fabsf((v).y)),                    \
                         fmaxf(fabsf((v).z), fabsf((v).w)));                   \
        _m = fmaxf(_m, __shfl_xor_sync(0xffffffffu, _m, 1));                   \
        _m = fmaxf(_m, __shfl_xor_sync(0xffffffffu, _m, 2));                   \
        uint32_t _eb = __float_as_uint(_m) & 0x7f800000u;                      \
        float _inv = __uint_as_float(0x82000000u - _eb);   /* 2^(6-e) */       \
        float _scl = __uint_as_float(_eb - 0x03000000u);   /* 2^(e-6) */       \
        float _q0 = (fminf(fmaf((v).x, _inv, 12582912.f), 12583039.f) - 12582912.f) * _scl; \
        float _q1 = (fminf(fmaf((v).y, _inv, 12582912.f), 12583039.f) - 12582912.f) * _scl; \
        float _q2 = (fminf(fmaf((v).z, _inv, 12582912.f), 12583039.f) - 12582912.f) * _scl; \
        float _q3 = (fminf(fmaf((v).w, _inv, 12582912.f), 12583039.f) - 12582912.f) * _scl; \
        uint32_t _p0, _p1;                                                     \
        asm("cvt.rn.satfinite.bf16x2.f32 %0, %1, %2;" : "=r"(_p0) : "f"(_q1), "f"(_q0)); \
        asm("cvt.rn.satfinite.bf16x2.f32 %0, %1, %2;" : "=r"(_p1) : "f"(_q3), "f"(_q2)); \
        asm volatile("st.shared.v2.b32 [%0], {%1,%2};"                         \
                     :: "r"(saddr), "r"(_p0), "r"(_p1) : "memory");            \
    } while (0)

// ===================== fused BFP GEMM ======================================
__global__ void __launch_bounds__(256, 1)
bfp_gemm_fused(const float* __restrict__ x, const float* __restrict__ w,
               const float* __restrict__ bias, float* __restrict__ out) {
    extern __shared__ char smem[];
    uint32_t sb = smem_u32(smem);
    int tid = threadIdx.x;
    int wid = tid >> 5;
    int lid = tid & 31;
    int wm = wid & 1;        // M warp: 0..1 (64 rows each)
    int wn = wid >> 1;       // N warp: 0..3 (64 cols each)
    int tile_n = blockIdx.x; // 0..15
    int tile_m = blockIdx.y; // 0..31

    // ---- coalesced quant-duty mapping: row t>>4 (+16i), float4-col t&15 ----
    int qr = tid >> 4;
    int qc = tid & 15;
    const float4* aP = (const float4*)x + (size_t)(tile_m * BM + qr) * (GK / 4) + qc;
    const float4* bP = (const float4*)w + (size_t)(tile_n * BN + qr) * (GK / 4) + qc;
    const size_t rstep = (size_t)16 * (GK / 4);
    // SW128 swizzle; mask invariant across +16-row units (16 = 0 mod 8)
    uint32_t sts0 = ((uint32_t)(qr * 128 + qc * 8)) ^ ((uint32_t)(qr & 7) << 4);

    // ---- ldmatrix address components (128B rows, SW128 XOR) ----
    uint32_t a_kx = (uint32_t)((lid >> 4) << 4);
    uint32_t a_off[4], a_mk[4];
#pragma unroll
    for (int am = 0; am < 4; am++) {
        int r = wm * 64 + am * 16 + (lid & 15);
        a_off[am] = (uint32_t)r * 128u;
        a_mk[am]  = (uint32_t)(r & 7) << 4;
    }
    uint32_t b_kx = (uint32_t)(((lid >> 3) & 1) << 4);
    uint32_t b_off[4], b_mk[4];
#pragma unroll
    for (int bn = 0; bn < 4; bn++) {
        int r = wn * 64 + bn * 16 + ((lid >> 4) & 1) * 8 + (lid & 7);
        b_off[bn] = (uint32_t)r * 128u;
        b_mk[bn]  = (uint32_t)(r & 7) << 4;
    }

    float acc[4][8][4];
#pragma unroll
    for (int am = 0; am < 4; am++)
#pragma unroll
        for (int j = 0; j < 8; j++)
#pragma unroll
            for (int c = 0; c < 4; c++) acc[am][j][c] = 0.f;

    // staged fp32: A 8 units; B in two 8-unit halves (rows 0..127 / 128..255)
    float4 fa[8], fb0[8], fb1[8];

#define LOAD_A(kt)  do { _Pragma("unroll") \
        for (int i = 0; i < 8; i++) fa[i]  = aP[(size_t)(kt) * 16 + i * rstep]; } while (0)
#define LOAD_B0(kt) do { _Pragma("unroll") \
        for (int i = 0; i < 8; i++) fb0[i] = bP[(size_t)(kt) * 16 + i * rstep]; } while (0)
#define LOAD_B1(kt) do { _Pragma("unroll") \
        for (int i = 0; i < 8; i++) fb1[i] = bP[(size_t)(kt) * 16 + (i + 8) * rstep]; } while (0)
#define Q_A(dst)  do { _Pragma("unroll") \
        for (int i = 0; i < 8; i++) QUNIT(fa[i],  (dst) + sts0 + (uint32_t)(i * 2048)); } while (0)
#define Q_B0(dst) do { _Pragma("unroll") \
        for (int i = 0; i < 8; i++) QUNIT(fb0[i], (dst) + A_TILE + sts0 + (uint32_t)(i * 2048)); } while (0)
#define Q_B1(dst) do { _Pragma("unroll") \
        for (int i = 0; i < 8; i++) QUNIT(fb1[i], (dst) + A_TILE + sts0 + (uint32_t)(16384 + i * 2048)); } while (0)

    // ---- prologue: tile 0 into buffer 0 ----
    LOAD_A(0); LOAD_B0(0); LOAD_B1(0);
    Q_A(sb); Q_B0(sb); Q_B1(sb);
    __syncthreads();

    // ---- main loop ----
    for (int kt = 0; kt < KTILES; kt++) {
        uint32_t cur = sb + (uint32_t)(kt & 1) * STAGE;
        uint32_t nxt = sb + (uint32_t)((kt + 1) & 1) * STAGE;
        uint32_t Bb = cur + A_TILE;
        bool more = (kt + 1 < KTILES);

        if (more) { LOAD_A(kt + 1); LOAD_B0(kt + 1); }

#define KS_PHASE(ks) do {                                                      \
            uint32_t ko = (uint32_t)(ks) * 32u;                                \
            uint32_t A[4][4], B[4][4];                                         \
            _Pragma("unroll")                                                  \
            for (int am = 0; am < 4; am++)                                     \
                LDM_X4(A[am][0], A[am][1], A[am][2], A[am][3],                 \
                       cur + a_off[am] + ((ko + a_kx) ^ a_mk[am]));            \
            _Pragma("unroll")                                                  \
            for (int bn = 0; bn < 4; bn++)                                     \
                LDM_X4(B[bn][0], B[bn][1], B[bn][2], B[bn][3],                 \
                       Bb + b_off[bn] + ((ko + b_kx) ^ b_mk[bn]));             \
            _Pragma("unroll")                                                  \
            for (int am = 0; am < 4; am++)                                     \
                _Pragma("unroll")                                              \
                for (int j = 0; j < 8; j++)                                    \
                    MMA16816(acc[am][j][0], acc[am][j][1], acc[am][j][2], acc[am][j][3], \
                             A[am][0], A[am][1], A[am][2], A[am][3],           \
                             B[j >> 1][(j & 1) * 2], B[j >> 1][(j & 1) * 2 + 1]); \
        } while (0)

        KS_PHASE(0);
        if (more) Q_A(nxt);
        KS_PHASE(1);
        if (more) { LOAD_B1(kt + 1); Q_B0(nxt); }
        KS_PHASE(2);
        if (more) Q_B1(nxt);
        KS_PHASE(3);
#undef KS_PHASE
        __syncthreads();
    }

    // ---- epilogue ----
#pragma unroll
    for (int am = 0; am < 4; am++) {
        int row0 = tile_m * BM + wm * 64 + am * 16 + (lid >> 2);
#pragma unroll
        for (int j = 0; j < 8; j++) {
            int col = tile_n * BN + wn * 64 + j * 8 + (lid & 3) * 2;
            float2 b2 = *(const float2*)(bias + col);
            float2 v0 = make_float2(acc[am][j][0] + b2.x, acc[am][j][1] + b2.y);
            float2 v1 = make_float2(acc[am][j][2] + b2.x, acc[am][j][3] + b2.y);
            *(float2*)(out + (size_t)row0 * GN + col)       = v0;
            *(float2*)(out + (size_t)(row0 + 8) * GN + col) = v1;
        }
    }
}

// ===================== launch =====================
extern "C" void kernel_launch(void* const* d_in, const int* in_sizes, int n_in,
                              void* d_out, int out_size) {
    const float* x    = (const float*)d_in[0];   // [4096, 4096]
    const float* w    = (const float*)d_in[1];   // [4096, 4096]
    const float* bias = (const float*)d_in[2];   // [4096]
    float* out = (float*)d_out;                  // [4096, 4096]

    (void)in_sizes; (void)n_in; (void)out_size;

    static bool attr_done = false;
    if (!attr_done) {
        cudaFuncSetAttribute(bfp_gemm_fused,
                             cudaFuncAttributeMaxDynamicSharedMemorySize, SMEM_TOTAL);
        attr_done = true;
    }

    dim3 grid(GN / BN, GM / BM);  // (16, 32)
    bfp_gemm_fused<<<grid, 256, SMEM_TOTAL>>>(x, w, bias, out);
}

// round 14
// speedup vs baseline: 1.2078x; 1.1042x over previous
#include <cuda_runtime.h>
#include <cuda_bf16.h>
#include <cstdint>

// ===================== problem constants =====================
static constexpr int GM = 4096, GN = 4096, GK = 4096;

// CTA 128x256, 8 warps as 2(M) x 4(N), warp tile 64x64, K-stage 64.
// Fused BFP quant; double-buffered bf16 smem (96KB).
static constexpr int BM = 128;
static constexpr int BN = 256;
static constexpr int BK = 64;
static constexpr int KTILES = GK / BK;            // 64

static constexpr int A_TILE = BM * BK * 2;        // 16384
static constexpr int B_TILE = BN * BK * 2;        // 32768
static constexpr int STAGE  = A_TILE + B_TILE;    // 49152
static constexpr int SMEM_TOTAL = 2 * STAGE;      // 98304

// ===================== PTX helpers =====================
__device__ __forceinline__ uint32_t smem_u32(const void* p) {
    uint32_t a;
    asm("{ .reg .u64 t; cvta.to.shared.u64 t, %1; cvt.u32.u64 %0, t; }" : "=r"(a) : "l"(p));
    return a;
}

#define LDM_X4(r0, r1, r2, r3, addr) \
    asm volatile("ldmatrix.sync.aligned.m8n8.x4.shared.b16 {%0,%1,%2,%3}, [%4];" \
                 : "=r"(r0), "=r"(r1), "=r"(r2), "=r"(r3) : "r"(addr))

#define MMA16816(d0, d1, d2, d3, a0, a1, a2, a3, b0, b1) \
    asm volatile( \
        "mma.sync.aligned.m16n8k16.row.col.f32.bf16.bf16.f32 " \
        "{%0,%1,%2,%3}, {%4,%5,%6,%7}, {%8,%9}, {%0,%1,%2,%3};" \
        : "+f"(d0), "+f"(d1), "+f"(d2), "+f"(d3) \
        : "r"(a0), "r"(a1), "r"(a2), "r"(a3), "r"(b0), "r"(b1))

// Quantize one float4 (quarter of a 16-float BFP group shared by a lane quad)
// and store 8B to swizzled smem. Exact round-half-even via magic-add; x*inv
// exact (power-of-2 scale); single upper clamp (+127); -128 unreachable.
#define QUNIT(v, saddr) do {                                                   \
        float _m = fmaxf(fmaxf(fabsf((v).x), fabsf((v).y)),                    \
                         fmaxf(fabsf((v).z), fabsf((v).w)));                   \
        _m = fmaxf(_m, __shfl_xor_sync(0xffffffffu, _m, 1));                   \
        _m = fmaxf(_m, __shfl_xor_sync(0xffffffffu, _m, 2));                   \
        uint32_t _eb = __float_as_uint(_m) & 0x7f800000u;                      \
        float _inv = __uint_as_float(0x82000000u - _eb);   /* 2^(6-e) */       \
        float _scl = __uint_as_float(_eb - 0x03000000u);   /* 2^(e-6) */       \
        float _q0 = (fminf(fmaf((v).x, _inv, 12582912.f), 12583039.f) - 12582912.f) * _scl; \
        float _q1 = (fminf(fmaf((v).y, _inv, 12582912.f), 12583039.f) - 12582912.f) * _scl; \
        float _q2 = (fminf(fmaf((v).z, _inv, 12582912.f), 12583039.f) - 12582912.f) * _scl; \
        float _q3 = (fminf(fmaf((v).w, _inv, 12582912.f), 12583039.f) - 12582912.f) * _scl; \
        uint32_t _p0, _p1;                                                     \
        asm("cvt.rn.satfinite.bf16x2.f32 %0, %1, %2;" : "=r"(_p0) : "f"(_q1), "f"(_q0)); \
        asm("cvt.rn.satfinite.bf16x2.f32 %0, %1, %2;" : "=r"(_p1) : "f"(_q3), "f"(_q2)); \
        asm volatile("st.shared.v2.b32 [%0], {%1,%2};"                         \
                     :: "r"(saddr), "r"(_p0), "r"(_p1) : "memory");            \
    } while (0)

// ===================== fused BFP GEMM ======================================
// Register-pressure-phased staging: three disjoint 8-float4 windows per
// iteration (A, B-half0, B-half1), each loaded right after the previous
// window's quant frees its registers, each covered by one KS MMA phase.
__global__ void __launch_bounds__(256, 1)
bfp_gemm_fused(const float* __restrict__ x, const float* __restrict__ w,
               const float* __restrict__ bias, float* __restrict__ out) {
    extern __shared__ char smem[];
    uint32_t sb = smem_u32(smem);
    int tid = threadIdx.x;
    int wid = tid >> 5;
    int lid = tid & 31;
    int wm = wid & 1;        // M warp: 0..1 (64 rows each)
    int wn = wid >> 1;       // N warp: 0..3 (64 cols each)
    int tile_n = blockIdx.x; // 0..15
    int tile_m = blockIdx.y; // 0..31

    // ---- coalesced quant-duty mapping: row t>>4 (+16i), float4-col t&15 ----
    int qr = tid >> 4;
    int qc = tid & 15;
    const float4* aP = (const float4*)x + (size_t)(tile_m * BM + qr) * (GK / 4) + qc;
    const float4* bP = (const float4*)w + (size_t)(tile_n * BN + qr) * (GK / 4) + qc;
    const size_t rstep = (size_t)16 * (GK / 4);
    // SW128 swizzle; mask invariant across +16-row units (16 = 0 mod 8)
    uint32_t sts0 = ((uint32_t)(qr * 128 + qc * 8)) ^ ((uint32_t)(qr & 7) << 4);

    // ---- ldmatrix address components (128B rows, SW128 XOR) ----
    uint32_t a_kx = (uint32_t)((lid >> 4) << 4);
    uint32_t a_off[4], a_mk[4];
#pragma unroll
    for (int am = 0; am < 4; am++) {
        int r = wm * 64 + am * 16 + (lid & 15);
        a_off[am] = (uint32_t)r * 128u;
        a_mk[am]  = (uint32_t)(r & 7) << 4;
    }
    uint32_t b_kx = (uint32_t)(((lid >> 3) & 1) << 4);
    uint32_t b_off[4], b_mk[4];
#pragma unroll
    for (int bn = 0; bn < 4; bn++) {
        int r = wn * 64 + bn * 16 + ((lid >> 4) & 1) * 8 + (lid & 7);
        b_off[bn] = (uint32_t)r * 128u;
        b_mk[bn]  = (uint32_t)(r & 7) << 4;
    }

    float acc[4][8][4];
#pragma unroll
    for (int am = 0; am < 4; am++)
#pragma unroll
        for (int j = 0; j < 8; j++)
#pragma unroll
            for (int c = 0; c < 4; c++) acc[am][j][c] = 0.f;

    // single 8-float4 staging window, reused across the 3 phases
    float4 st[8];

#define LOAD_W(basePtr, kt, ofs) do { _Pragma("unroll") \
        for (int i = 0; i < 8; i++) st[i] = (basePtr)[(size_t)(kt) * 16 + (i + (ofs)) * rstep]; } while (0)
#define Q_W(dstAddr) do { _Pragma("unroll") \
        for (int i = 0; i < 8; i++) QUNIT(st[i], (dstAddr) + (uint32_t)(i * 2048)); } while (0)

#define KS_PHASE(ks) do {                                                      \
            uint32_t ko = (uint32_t)(ks) * 32u;                                \
            uint32_t A[4][4], B[4][4];                                         \
            _Pragma("unroll")                                                  \
            for (int am = 0; am < 4; am++)                                     \
                LDM_X4(A[am][0], A[am][1], A[am][2], A[am][3],                 \
                       cur + a_off[am] + ((ko + a_kx) ^ a_mk[am]));            \
            _Pragma("unroll")                                                  \
            for (int bn = 0; bn < 4; bn++)                                     \
                LDM_X4(B[bn][0], B[bn][1], B[bn][2], B[bn][3],                 \
                       cur + A_TILE + b_off[bn] + ((ko + b_kx) ^ b_mk[bn]));   \
            _Pragma("unroll")                                                  \
            for (int am = 0; am < 4; am++)                                     \
                _Pragma("unroll")                                              \
                for (int j = 0; j < 8; j++)                                    \
                    MMA16816(acc[am][j][0], acc[am][j][1], acc[am][j][2], acc[am][j][3], \
                             A[am][0], A[am][1], A[am][2], A[am][3],           \
                             B[j >> 1][(j & 1) * 2], B[j >> 1][(j & 1) * 2 + 1]); \
        } while (0)

    // ---- prologue: tile 0 into buffer 0 ----
    LOAD_W(aP, 0, 0);  Q_W(sb + sts0);
    LOAD_W(bP, 0, 0);  Q_W(sb + A_TILE + sts0);
    LOAD_W(bP, 0, 8);  Q_W(sb + A_TILE + 16384u + sts0);
    __syncthreads();

    // ---- main loop ----
    for (int kt = 0; kt < KTILES; kt++) {
        uint32_t cur = sb + (uint32_t)(kt & 1) * STAGE;
        uint32_t nxt = sb + (uint32_t)((kt + 1) & 1) * STAGE;
        bool more = (kt + 1 < KTILES);

        if (more) LOAD_W(aP, kt + 1, 0);          // A window in flight
        KS_PHASE(0);                               // covers A LDG
        if (more) { Q_W(nxt + sts0); LOAD_W(bP, kt + 1, 0); }  // free A, load B0
        KS_PHASE(1);                               // covers B0 LDG
        if (more) { Q_W(nxt + A_TILE + sts0); LOAD_W(bP, kt + 1, 8); }
        KS_PHASE(2);                               // covers B1 LDG
        if (more) Q_W(nxt + A_TILE + 16384u + sts0);
        KS_PHASE(3);
        __syncthreads();
    }
#undef KS_PHASE
#undef LOAD_W
#undef Q_W

    // ---- epilogue ----
#pragma unroll
    for (int am = 0; am < 4; am++) {
        int row0 = tile_m * BM + wm * 64 + am * 16 + (lid >> 2);
#pragma unroll
        for (int j = 0; j < 8; j++) {
            int col = tile_n * BN + wn * 64 + j * 8 + (lid & 3) * 2;
            float2 b2 = *(const float2*)(bias + col);
            float2 v0 = make_float2(acc[am][j][0] + b2.x, acc[am][j][1] + b2.y);
            float2 v1 = make_float2(acc[am][j][2] + b2.x, acc[am][j][3] + b2.y);
            *(float2*)(out + (size_t)row0 * GN + col)       = v0;
            *(float2*)(out + (size_t)(row0 + 8) * GN + col) = v1;
        }
    }
}

// ===================== launch =====================
extern "C" void kernel_launch(void* const* d_in, const int* in_sizes, int n_in,
                              void* d_out, int out_size) {
    const float* x    = (const float*)d_in[0];   // [4096, 4096]
    const float* w    = (const float*)d_in[1];   // [4096, 4096]
    const float* bias = (const float*)d_in[2];   // [4096]
    float* out = (float*)d_out;                  // [4096, 4096]

    (void)in_sizes; (void)n_in; (void)out_size;

    static bool attr_done = false;
    if (!attr_done) {
        cudaFuncSetAttribute(bfp_gemm_fused,
                             cudaFuncAttributeMaxDynamicSharedMemorySize, SMEM_TOTAL);
        attr_done = true;
    }

    dim3 grid(GN / BN, GM / BM);  // (16, 32)
    bfp_gemm_fused<<<grid, 256, SMEM_TOTAL>>>(x, w, bias, out);
}

// round 15
// speedup vs baseline: 1.2776x; 1.0579x over previous
#include <cuda_runtime.h>
#include <cuda_bf16.h>
#include <cstdint>

// ===================== problem constants =====================
static constexpr int GM = 4096, GN = 4096, GK = 4096;

// CTA 128x256, 16 warps as 4(M) x 4(N), warp tile 32x64, K-stage 64.
// 512 threads -> 16 warps/SM = 4 per SMSP (2x the latency hiding of R14).
static constexpr int BM = 128;
static constexpr int BN = 256;
static constexpr int BK = 64;
static constexpr int KTILES = GK / BK;            // 64

static constexpr int A_TILE = BM * BK * 2;        // 16384
static constexpr int B_TILE = BN * BK * 2;        // 32768
static constexpr int STAGE  = A_TILE + B_TILE;    // 49152
static constexpr int SMEM_TOTAL = 2 * STAGE;      // 98304

// ===================== PTX helpers =====================
__device__ __forceinline__ uint32_t smem_u32(const void* p) {
    uint32_t a;
    asm("{ .reg .u64 t; cvta.to.shared.u64 t, %1; cvt.u32.u64 %0, t; }" : "=r"(a) : "l"(p));
    return a;
}

#define LDM_X4(r0, r1, r2, r3, addr) \
    asm volatile("ldmatrix.sync.aligned.m8n8.x4.shared.b16 {%0,%1,%2,%3}, [%4];" \
                 : "=r"(r0), "=r"(r1), "=r"(r2), "=r"(r3) : "r"(addr))

#define MMA16816(d0, d1, d2, d3, a0, a1, a2, a3, b0, b1) \
    asm volatile( \
        "mma.sync.aligned.m16n8k16.row.col.f32.bf16.bf16.f32 " \
        "{%0,%1,%2,%3}, {%4,%5,%6,%7}, {%8,%9}, {%0,%1,%2,%3};" \
        : "+f"(d0), "+f"(d1), "+f"(d2), "+f"(d3) \
        : "r"(a0), "r"(a1), "r"(a2), "r"(a3), "r"(b0), "r"(b1))

// Quantize one float4 (quarter of a 16-float BFP group shared by a lane quad)
// and store 8B to swizzled smem. Exact round-half-even via magic-add; x*inv
// exact (power-of-2 scale); single upper clamp (+127); -128 unreachable.
#define QUNIT(v, saddr) do {                                                   \
        float _m = fmaxf(fmaxf(fabsf((v).x), fabsf((v).y)),                    \
                         fmaxf(fabsf((v).z), fabsf((v).w)));                   \
        _m = fmaxf(_m, __shfl_xor_sync(0xffffffffu, _m, 1));                   \
        _m = fmaxf(_m, __shfl_xor_sync(0xffffffffu, _m, 2));                   \
        uint32_t _eb = __float_as_uint(_m) & 0x7f800000u;                      \
        float _inv = __uint_as_float(0x82000000u - _eb);   /* 2^(6-e) */       \
        float _scl = __uint_as_float(_eb - 0x03000000u);   /* 2^(e-6) */       \
        float _q0 = (fminf(fmaf((v).x, _inv, 12582912.f), 12583039.f) - 12582912.f) * _scl; \
        float _q1 = (fminf(fmaf((v).y, _inv, 12582912.f), 12583039.f) - 12582912.f) * _scl; \
        float _q2 = (fminf(fmaf((v).z, _inv, 12582912.f), 12583039.f) - 12582912.f) * _scl; \
        float _q3 = (fminf(fmaf((v).w, _inv, 12582912.f), 12583039.f) - 12582912.f) * _scl; \
        uint32_t _p0, _p1;                                                     \
        asm("cvt.rn.satfinite.bf16x2.f32 %0, %1, %2;" : "=r"(_p0) : "f"(_q1), "f"(_q0)); \
        asm("cvt.rn.satfinite.bf16x2.f32 %0, %1, %2;" : "=r"(_p1) : "f"(_q3), "f"(_q2)); \
        asm volatile("st.shared.v2.b32 [%0], {%1,%2};"                         \
                     :: "r"(saddr), "r"(_p0), "r"(_p1) : "memory");            \
    } while (0)

// ===================== fused BFP GEMM ======================================
__global__ void __launch_bounds__(512, 1)
bfp_gemm_fused(const float* __restrict__ x, const float* __restrict__ w,
               const float* __restrict__ bias, float* __restrict__ out) {
    extern __shared__ char smem[];
    uint32_t sb = smem_u32(smem);
    int tid = threadIdx.x;
    int wid = tid >> 5;
    int lid = tid & 31;
    int wm = wid & 3;        // M warp: 0..3 (32 rows each)
    int wn = wid >> 2;       // N warp: 0..3 (64 cols each)
    int tile_n = blockIdx.x; // 0..15
    int tile_m = blockIdx.y; // 0..31

    // ---- quant-duty mapping: row tid>>4 (+32i), float4-col tid&15 ----
    // A: 4 units/thread (i<4); B: 8 units/thread (i<8), handled as two 4-unit
    // windows. 32-row unit stride keeps swizzle mask invariant (32 = 0 mod 8).
    int qr = tid >> 4;                // 0..31
    int qc = tid & 15;
    const float4* aP = (const float4*)x + (size_t)(tile_m * BM + qr) * (GK / 4) + qc;
    const float4* bP = (const float4*)w + (size_t)(tile_n * BN + qr) * (GK / 4) + qc;
    const size_t rstep = (size_t)32 * (GK / 4);
    uint32_t sts0 = ((uint32_t)(qr * 128 + qc * 8)) ^ ((uint32_t)(qr & 7) << 4);

    // ---- ldmatrix address components (128B rows, SW128 XOR) ----
    uint32_t a_kx = (uint32_t)((lid >> 4) << 4);
    uint32_t a_off[2], a_mk[2];
#pragma unroll
    for (int am = 0; am < 2; am++) {
        int r = wm * 32 + am * 16 + (lid & 15);
        a_off[am] = (uint32_t)r * 128u;
        a_mk[am]  = (uint32_t)(r & 7) << 4;
    }
    uint32_t b_kx = (uint32_t)(((lid >> 3) & 1) << 4);
    uint32_t b_off[4], b_mk[4];
#pragma unroll
    for (int bn = 0; bn < 4; bn++) {
        int r = wn * 64 + bn * 16 + ((lid >> 4) & 1) * 8 + (lid & 7);
        b_off[bn] = (uint32_t)r * 128u;
        b_mk[bn]  = (uint32_t)(r & 7) << 4;
    }

    float acc[2][8][4];
#pragma unroll
    for (int am = 0; am < 2; am++)
#pragma unroll
        for (int j = 0; j < 8; j++)
#pragma unroll
            for (int c = 0; c < 4; c++) acc[am][j][c] = 0.f;

    // single 4-float4 staging window, reused across three phases per iter
    float4 st[4];

#define LOAD_W(basePtr, kt, ofs) do { _Pragma("unroll") \
        for (int i = 0; i < 4; i++) st[i] = (basePtr)[(size_t)(kt) * 16 + (i + (ofs)) * rstep]; } while (0)
#define Q_W(dstAddr) do { _Pragma("unroll") \
        for (int i = 0; i < 4; i++) QUNIT(st[i], (dstAddr) + (uint32_t)(i * 4096)); } while (0)

#define KS_PHASE(ks) do {                                                      \
            uint32_t ko = (uint32_t)(ks) * 32u;                                \
            uint32_t A[2][4], B[4][4];                                         \
            _Pragma("unroll")                                                  \
            for (int am = 0; am < 2; am++)                                     \
                LDM_X4(A[am][0], A[am][1], A[am][2], A[am][3],                 \
                       cur + a_off[am] + ((ko + a_kx) ^ a_mk[am]));            \
            _Pragma("unroll")                                                  \
            for (int bn = 0; bn < 4; bn++)                                     \
                LDM_X4(B[bn][0], B[bn][1], B[bn][2], B[bn][3],                 \
                       cur + A_TILE + b_off[bn] + ((ko + b_kx) ^ b_mk[bn]));   \
            _Pragma("unroll")                                                  \
            for (int am = 0; am < 2; am++)                                     \
                _Pragma("unroll")                                              \
                for (int j = 0; j < 8; j++)                                    \
                    MMA16816(acc[am][j][0], acc[am][j][1], acc[am][j][2], acc[am][j][3], \
                             A[am][0], A[am][1], A[am][2], A[am][3],           \
                             B[j >> 1][(j & 1) * 2], B[j >> 1][(j & 1) * 2 + 1]); \
        } while (0)

    // ---- prologue: tile 0 into buffer 0 ----
    LOAD_W(aP, 0, 0);  Q_W(sb + sts0);
    LOAD_W(bP, 0, 0);  Q_W(sb + A_TILE + sts0);
    LOAD_W(bP, 0, 4);  Q_W(sb + A_TILE + 16384u + sts0);
    __syncthreads();

    // ---- main loop ----
    for (int kt = 0; kt < KTILES; kt++) {
        uint32_t cur = sb + (uint32_t)(kt & 1) * STAGE;
        uint32_t nxt = sb + (uint32_t)((kt + 1) & 1) * STAGE;
        bool more = (kt + 1 < KTILES);

        if (more) LOAD_W(aP, kt + 1, 0);          // A window in flight
        KS_PHASE(0);                               // covers A LDG
        if (more) { Q_W(nxt + sts0); LOAD_W(bP, kt + 1, 0); }  // free A, load B0
        KS_PHASE(1);                               // covers B0 LDG
        if (more) { Q_W(nxt + A_TILE + sts0); LOAD_W(bP, kt + 1, 4); }
        KS_PHASE(2);                               // covers B1 LDG
        if (more) Q_W(nxt + A_TILE + 16384u + sts0);
        KS_PHASE(3);
        __syncthreads();
    }
#undef KS_PHASE
#undef LOAD_W
#undef Q_W

    // ---- epilogue ----
#pragma unroll
    for (int am = 0; am < 2; am++) {
        int row0 = tile_m * BM + wm * 32 + am * 16 + (lid >> 2);
#pragma unroll
        for (int j = 0; j < 8; j++) {
            int col = tile_n * BN + wn * 64 + j * 8 + (lid & 3) * 2;
            float2 b2 = *(const float2*)(bias + col);
            float2 v0 = make_float2(acc[am][j][0] + b2.x, acc[am][j][1] + b2.y);
            float2 v1 = make_float2(acc[am][j][2] + b2.x, acc[am][j][3] + b2.y);
            *(float2*)(out + (size_t)row0 * GN + col)       = v0;
            *(float2*)(out + (size_t)(row0 + 8) * GN + col) = v1;
        }
    }
}

// ===================== launch =====================
extern "C" void kernel_launch(void* const* d_in, const int* in_sizes, int n_in,
                              void* d_out, int out_size) {
    const float* x    = (const float*)d_in[0];   // [4096, 4096]
    const float* w    = (const float*)d_in[1];   // [4096, 4096]
    const float* bias = (const float*)d_in[2];   // [4096]
    float* out = (float*)d_out;                  // [4096, 4096]

    (void)in_sizes; (void)n_in; (void)out_size;

    static bool attr_done = false;
    if (!attr_done) {
        cudaFuncSetAttribute(bfp_gemm_fused,
                             cudaFuncAttributeMaxDynamicSharedMemorySize, SMEM_TOTAL);
        attr_done = true;
    }

    dim3 grid(GN / BN, GM / BM);  // (16, 32)
    bfp_gemm_fused<<<grid, 512, SMEM_TOTAL>>>(x, w, bias, out);
}

// round 16
// speedup vs baseline: 1.3748x; 1.0761x over previous
#include <cuda_runtime.h>
#include <cuda_bf16.h>
#include <cstdint>

// ===================== problem constants =====================
static constexpr int GM = 4096, GN = 4096, GK = 4096;

// CTA 128x256, 16 warps as 4(M) x 4(N), warp tile 32x64, K-stage 64.
// 4-stage smem ring, barrier every other iteration (produce 2 tiles ahead).
static constexpr int BM = 128;
static constexpr int BN = 256;
static constexpr int BK = 64;
static constexpr int KTILES = GK / BK;            // 64

static constexpr int A_TILE = BM * BK * 2;        // 16384
static constexpr int B_TILE = BN * BK * 2;        // 32768
static constexpr int STAGE  = A_TILE + B_TILE;    // 49152
static constexpr int SMEM_TOTAL = 4 * STAGE;      // 196608 (<= 227KB cap)

// ===================== PTX helpers =====================
__device__ __forceinline__ uint32_t smem_u32(const void* p) {
    uint32_t a;
    asm("{ .reg .u64 t; cvta.to.shared.u64 t, %1; cvt.u32.u64 %0, t; }" : "=r"(a) : "l"(p));
    return a;
}

#define LDM_X4(r0, r1, r2, r3, addr) \
    asm volatile("ldmatrix.sync.aligned.m8n8.x4.shared.b16 {%0,%1,%2,%3}, [%4];" \
                 : "=r"(r0), "=r"(r1), "=r"(r2), "=r"(r3) : "r"(addr))

#define MMA16816(d0, d1, d2, d3, a0, a1, a2, a3, b0, b1) \
    asm volatile( \
        "mma.sync.aligned.m16n8k16.row.col.f32.bf16.bf16.f32 " \
        "{%0,%1,%2,%3}, {%4,%5,%6,%7}, {%8,%9}, {%0,%1,%2,%3};" \
        : "+f"(d0), "+f"(d1), "+f"(d2), "+f"(d3) \
        : "r"(a0), "r"(a1), "r"(a2), "r"(a3), "r"(b0), "r"(b1))

// Quantize one float4 (quarter of a 16-float BFP group shared by a lane quad)
// and store 8B to swizzled smem. Exact round-half-even via magic-add; x*inv
// exact (power-of-2 scale); single upper clamp (+127); -128 unreachable.
#define QUNIT(v, saddr) do {                                                   \
        float _m = fmaxf(fmaxf(fabsf((v).x), fabsf((v).y)),                    \
                         fmaxf(fabsf((v).z), fabsf((v).w)));                   \
        _m = fmaxf(_m, __shfl_xor_sync(0xffffffffu, _m, 1));                   \
        _m = fmaxf(_m, __shfl_xor_sync(0xffffffffu, _m, 2));                   \
        uint32_t _eb = __float_as_uint(_m) & 0x7f800000u;                      \
        float _inv = __uint_as_float(0x82000000u - _eb);   /* 2^(6-e) */       \
        float _scl = __uint_as_float(_eb - 0x03000000u);   /* 2^(e-6) */       \
        float _q0 = (fminf(fmaf((v).x, _inv, 12582912.f), 12583039.f) - 12582912.f) * _scl; \
        float _q1 = (fminf(fmaf((v).y, _inv, 12582912.f), 12583039.f) - 12582912.f) * _scl; \
        float _q2 = (fminf(fmaf((v).z, _inv, 12582912.f), 12583039.f) - 12582912.f) * _scl; \
        float _q3 = (fminf(fmaf((v).w, _inv, 12582912.f), 12583039.f) - 12582912.f) * _scl; \
        uint32_t _p0, _p1;                                                     \
        asm("cvt.rn.satfinite.bf16x2.f32 %0, %1, %2;" : "=r"(_p0) : "f"(_q1), "f"(_q0)); \
        asm("cvt.rn.satfinite.bf16x2.f32 %0, %1, %2;" : "=r"(_p1) : "f"(_q3), "f"(_q2)); \
        asm volatile("st.shared.v2.b32 [%0], {%1,%2};"                         \
                     :: "r"(saddr), "r"(_p0), "r"(_p1) : "memory");            \
    } while (0)

// ===================== fused BFP GEMM ======================================
__global__ void __launch_bounds__(512, 1)
bfp_gemm_fused(const float* __restrict__ x, const float* __restrict__ w,
               const float* __restrict__ bias, float* __restrict__ out) {
    extern __shared__ char smem[];
    uint32_t sb = smem_u32(smem);
    int tid = threadIdx.x;
    int wid = tid >> 5;
    int lid = tid & 31;
    int wm = wid & 3;        // M warp: 0..3 (32 rows each)
    int wn = wid >> 2;       // N warp: 0..3 (64 cols each)
    int tile_n = blockIdx.x; // 0..15
    int tile_m = blockIdx.y; // 0..31

    // ---- quant-duty mapping: row tid>>4 (+32i), float4-col tid&15 ----
    int qr = tid >> 4;                // 0..31
    int qc = tid & 15;
    const float4* aP = (const float4*)x + (size_t)(tile_m * BM + qr) * (GK / 4) + qc;
    const float4* bP = (const float4*)w + (size_t)(tile_n * BN + qr) * (GK / 4) + qc;
    const size_t rstep = (size_t)32 * (GK / 4);
    uint32_t sts0 = ((uint32_t)(qr * 128 + qc * 8)) ^ ((uint32_t)(qr & 7) << 4);

    // ---- ldmatrix address components (128B rows, SW128 XOR) ----
    uint32_t a_kx = (uint32_t)((lid >> 4) << 4);
    uint32_t a_off[2], a_mk[2];
#pragma unroll
    for (int am = 0; am < 2; am++) {
        int r = wm * 32 + am * 16 + (lid & 15);
        a_off[am] = (uint32_t)r * 128u;
        a_mk[am]  = (uint32_t)(r & 7) << 4;
    }
    uint32_t b_kx = (uint32_t)(((lid >> 3) & 1) << 4);
    uint32_t b_off[4], b_mk[4];
#pragma unroll
    for (int bn = 0; bn < 4; bn++) {
        int r = wn * 64 + bn * 16 + ((lid >> 4) & 1) * 8 + (lid & 7);
        b_off[bn] = (uint32_t)r * 128u;
        b_mk[bn]  = (uint32_t)(r & 7) << 4;
    }

    float acc[2][8][4];
#pragma unroll
    for (int am = 0; am < 2; am++)
#pragma unroll
        for (int j = 0; j < 8; j++)
#pragma unroll
            for (int c = 0; c < 4; c++) acc[am][j][c] = 0.f;

    // single 4-float4 staging window, reused across three phases per iter
    float4 st[4];

#define LOAD_W(basePtr, kt, ofs) do { _Pragma("unroll") \
        for (int i = 0; i < 4; i++) st[i] = (basePtr)[(size_t)(kt) * 16 + (i + (ofs)) * rstep]; } while (0)
#define Q_W(dstAddr) do { _Pragma("unroll") \
        for (int i = 0; i < 4; i++) QUNIT(st[i], (dstAddr) + (uint32_t)(i * 4096)); } while (0)

#define KS_PHASE(ks) do {                                                      \
            uint32_t ko = (uint32_t)(ks) * 32u;                                \
            uint32_t A[2][4], B[4][4];                                         \
            _Pragma("unroll")                                                  \
            for (int am = 0; am < 2; am++)                                     \
                LDM_X4(A[am][0], A[am][1], A[am][2], A[am][3],                 \
                       cur + a_off[am] + ((ko + a_kx) ^ a_mk[am]));            \
            _Pragma("unroll")                                                  \
            for (int bn = 0; bn < 4; bn++)                                     \
                LDM_X4(B[bn][0], B[bn][1], B[bn][2], B[bn][3],                 \
                       cur + A_TILE + b_off[bn] + ((ko + b_kx) ^ b_mk[bn]));   \
            _Pragma("unroll")                                                  \
            for (int am = 0; am < 2; am++)                                     \
                _Pragma("unroll")                                              \
                for (int j = 0; j < 8; j++)                                    \
                    MMA16816(acc[am][j][0], acc[am][j][1], acc[am][j][2], acc[am][j][3], \
                             A[am][0], A[am][1], A[am][2], A[am][3],           \
                             B[j >> 1][(j & 1) * 2], B[j >> 1][(j & 1) * 2 + 1]); \
        } while (0)

    // ---- prologue: tiles 0 and 1 into buffers 0 and 1 ----
#pragma unroll
    for (int t = 0; t < 2; t++) {
        uint32_t dst = sb + (uint32_t)t * STAGE;
        LOAD_W(aP, t, 0);  Q_W(dst + sts0);
        LOAD_W(bP, t, 0);  Q_W(dst + A_TILE + sts0);
        LOAD_W(bP, t, 4);  Q_W(dst + A_TILE + 16384u + sts0);
    }
    __syncthreads();

    // ---- main loop: produce tile kt+2, consume tile kt, barrier on odd kt --
    for (int kt = 0; kt < KTILES; kt++) {
        uint32_t cur = sb + (uint32_t)(kt & 3) * STAGE;
        uint32_t nx2 = sb + (uint32_t)((kt + 2) & 3) * STAGE;
        bool more = (kt + 2 < KTILES);

        if (more) LOAD_W(aP, kt + 2, 0);          // A window in flight
        KS_PHASE(0);                               // covers A LDG
        if (more) { Q_W(nx2 + sts0); LOAD_W(bP, kt + 2, 0); }
        KS_PHASE(1);                               // covers B0 LDG
        if (more) { Q_W(nx2 + A_TILE + sts0); LOAD_W(bP, kt + 2, 4); }
        KS_PHASE(2);                               // covers B1 LDG
        if (more) Q_W(nx2 + A_TILE + 16384u + sts0);
        KS_PHASE(3);
        if (kt & 1) __syncthreads();               // one barrier per 2 iters
    }
#undef KS_PHASE
#undef LOAD_W
#undef Q_W

    // ---- epilogue ----
#pragma unroll
    for (int am = 0; am < 2; am++) {
        int row0 = tile_m * BM + wm * 32 + am * 16 + (lid >> 2);
#pragma unroll
        for (int j = 0; j < 8; j++) {
            int col = tile_n * BN + wn * 64 + j * 8 + (lid & 3) * 2;
            float2 b2 = *(const float2*)(bias + col);
            float2 v0 = make_float2(acc[am][j][0] + b2.x, acc[am][j][1] + b2.y);
            float2 v1 = make_float2(acc[am][j][2] + b2.x, acc[am][j][3] + b2.y);
            *(float2*)(out + (size_t)row0 * GN + col)       = v0;
            *(float2*)(out + (size_t)(row0 + 8) * GN + col) = v1;
        }
    }
}

// ===================== launch =====================
extern "C" void kernel_launch(void* const* d_in, const int* in_sizes, int n_in,
                              void* d_out, int out_size) {
    const float* x    = (const float*)d_in[0];   // [4096, 4096]
    const float* w    = (const float*)d_in[1];   // [4096, 4096]
    const float* bias = (const float*)d_in[2];   // [4096]
    float* out = (float*)d_out;                  // [4096, 4096]

    (void)in_sizes; (void)n_in; (void)out_size;

    static bool attr_done = false;
    if (!attr_done) {
        cudaFuncSetAttribute(bfp_gemm_fused,
                             cudaFuncAttributeMaxDynamicSharedMemorySize, SMEM_TOTAL);
        attr_done = true;
    }

    dim3 grid(GN / BN, GM / BM);  // (16, 32)
    bfp_gemm_fused<<<grid, 512, SMEM_TOTAL>>>(x, w, bias, out);
}